// round 15
// baseline (speedup 1.0000x reference)
#include <cuda_runtime.h>
#include <cuda_bf16.h>
#include <cstdint>
#include <math.h>

// Problem shape (fixed by the reference)
#define BB 4
#define TT 2048
#define CC 1024
#define HH 1024

// ---------------------------------------------------------------------------
// Scratch (__device__ globals; allocation-free per harness rules)
// ---------------------------------------------------------------------------
__device__ __nv_bfloat16 g_xhi[(long)BB * TT * CC];
__device__ __nv_bfloat16 g_xlo[(long)BB * TT * CC];
__device__ __nv_bfloat16 g_wkhi[(long)HH * CC];
__device__ __nv_bfloat16 g_wklo[(long)HH * CC];
__device__ __nv_bfloat16 g_wvhi[(long)HH * CC];
__device__ __nv_bfloat16 g_wvlo[(long)HH * CC];
__device__ __nv_bfloat16 g_Khi[(long)BB * TT * HH];
__device__ __nv_bfloat16 g_Klo[(long)BB * TT * HH];
__device__ __nv_bfloat16 g_Vhi[(long)BB * TT * HH];   // natural [b][t][h]
__device__ __nv_bfloat16 g_Vlo[(long)BB * TT * HH];
__device__ float         g_S[(long)BB * TT * TT];
__device__ __nv_bfloat16 g_Phi[(long)BB * TT * TT];
__device__ __nv_bfloat16 g_Plo[(long)BB * TT * TT];

// ---------------------------------------------------------------------------
// PTX helpers (compute_103-safe: sm_80-era tensor ISA only)
// ---------------------------------------------------------------------------
__device__ __forceinline__ uint32_t smem_u32(const void* p) {
    uint32_t a;
    asm("{ .reg .u64 t; cvta.to.shared.u64 t, %1; cvt.u32.u64 %0, t; }"
        : "=r"(a) : "l"(p));
    return a;
}

__device__ __forceinline__ void cpa16(uint32_t s, const void* g) {
    asm volatile("cp.async.cg.shared.global [%0], [%1], 16;" :: "r"(s), "l"(g));
}
#define CP_COMMIT()  asm volatile("cp.async.commit_group;" ::: "memory")
#define CP_WAIT(n)   asm volatile("cp.async.wait_group %0;" :: "n"(n) : "memory")

#define LDSM4(r0, r1, r2, r3, addr) \
    asm volatile("ldmatrix.sync.aligned.m8n8.x4.shared.b16 {%0,%1,%2,%3}, [%4];" \
                 : "=r"(r0), "=r"(r1), "=r"(r2), "=r"(r3) : "r"(addr))

#define LDSM4T(r0, r1, r2, r3, addr) \
    asm volatile("ldmatrix.sync.aligned.m8n8.x4.trans.shared.b16 {%0,%1,%2,%3}, [%4];" \
                 : "=r"(r0), "=r"(r1), "=r"(r2), "=r"(r3) : "r"(addr))

#define MMA16816(c, a, b0, b1) \
    asm volatile("mma.sync.aligned.m16n8k16.row.col.f32.bf16.bf16.f32 " \
                 "{%0,%1,%2,%3}, {%4,%5,%6,%7}, {%8,%9}, {%0,%1,%2,%3};" \
                 : "+f"((c)[0]), "+f"((c)[1]), "+f"((c)[2]), "+f"((c)[3]) \
                 : "r"((a)[0]), "r"((a)[1]), "r"((a)[2]), "r"((a)[3]), \
                   "r"(b0), "r"(b1))

// ---------------------------------------------------------------------------
// HMMA GEMM, bf16x3 split precision, 2-stage cp.async pipeline.
// R13: cross-boundary deferral of ks1's lo*hi pass (reg-resident tensor work
// covering the sync/drain window). R14: ks0 A-fragment LDSMs are issued
// BEFORE the deferred pass so their latency hides under the deferred MMAs
// (asm volatile order is preserved by ptxas, so this ordering is real).
// Per-accumulator MMA order unchanged -> bit-identical numerics.
// MODE: 1 = causal triangular decode, 2 = k-bounded PV (bm reversed),
//       3 = fused dual projection (blockIdx.z selects B/C set)
// OUTMODE: 0 = fp32 C (scaled); 1 = bf16 hi/lo split into Chi/Clo
// BTRANS:  0 = B [n][k] NT; 1 = B [k][n] via ldmatrix.trans
// ---------------------------------------------------------------------------
#define GEMM_SMEM_BYTES (2 * 32768)

template <int BTRANS>
__device__ __forceinline__ void load_tiles(
    uint32_t sb, const __nv_bfloat16* __restrict__ Ah,
    const __nv_bfloat16* __restrict__ Al,
    const __nv_bfloat16* __restrict__ Bh,
    const __nv_bfloat16* __restrict__ Bl,
    int K, int N, int aRow0, int bRow0, int kh, int tid)
{
#pragma unroll
    for (int t = 0; t < 2; t++) {
        int idx = tid + t * 256;
        int row = idx >> 2;              // 0..127
        int c   = idx & 3;
        uint32_t off = (uint32_t)(row << 6) + ((uint32_t)(c ^ ((row >> 1) & 3)) << 4);
        long ga = (long)(aRow0 + row) * K + kh + c * 8;
        cpa16(sb + off,        Ah + ga);
        cpa16(sb + 8192 + off, Al + ga);
    }
    if (BTRANS == 0) {
#pragma unroll
        for (int t = 0; t < 2; t++) {
            int idx = tid + t * 256;
            int row = idx >> 2;
            int c   = idx & 3;
            uint32_t off = (uint32_t)(row << 6) + ((uint32_t)(c ^ ((row >> 1) & 3)) << 4);
            long gb = (long)(bRow0 + row) * K + kh + c * 8;
            cpa16(sb + 16384 + off, Bh + gb);
            cpa16(sb + 24576 + off, Bl + gb);
        }
    } else {
#pragma unroll
        for (int t = 0; t < 2; t++) {
            int idx = tid + t * 256;
            int row = idx >> 4;          // 0..31 (k)
            int c   = idx & 15;          // 16B chunk (8 n)
            uint32_t off = (uint32_t)(row << 8) + ((uint32_t)(c ^ (row & 7)) << 4);
            long gb = (long)(kh + row) * N + bRow0 + c * 8;
            cpa16(sb + 16384 + off, Bh + gb);
            cpa16(sb + 24576 + off, Bl + gb);
        }
    }
}

template <int MODE, int OUTMODE, int BTRANS>
__global__ void __launch_bounds__(256, 2)
mma_gemm(const __nv_bfloat16* __restrict__ Ahi, const __nv_bfloat16* __restrict__ Alo,
         const __nv_bfloat16* __restrict__ Bhi, const __nv_bfloat16* __restrict__ Blo,
         const __nv_bfloat16* __restrict__ Bhi2, const __nv_bfloat16* __restrict__ Blo2,
         float* __restrict__ C,
         __nv_bfloat16* __restrict__ Chi, __nv_bfloat16* __restrict__ Clo,
         __nv_bfloat16* __restrict__ Chi2, __nv_bfloat16* __restrict__ Clo2,
         int M, int N, int K, long sA, long sB, long sC, float scale)
{
    int bm, bn, bz;
    if (MODE == 1) {
        int i = blockIdx.x;
        bm = (int)((sqrtf(8.0f * (float)i + 1.0f) - 1.0f) * 0.5f);
        while ((bm + 1) * (bm + 2) / 2 <= i) bm++;
        while (bm * (bm + 1) / 2 > i) bm--;
        bn = i - bm * (bm + 1) / 2;
        bz = blockIdx.z;
    } else if (MODE == 3) {
        bm = blockIdx.y; bn = blockIdx.x; bz = 0;
        if (blockIdx.z) { Bhi = Bhi2; Blo = Blo2; Chi = Chi2; Clo = Clo2; }
    } else {
        bm = blockIdx.y; bn = blockIdx.x; bz = blockIdx.z;
        if (MODE == 2) bm = gridDim.y - 1 - bm;   // longest-k tiles first
    }

    extern __shared__ __align__(1024) char smem[];
    uint32_t sbase = smem_u32(smem);

    const __nv_bfloat16* Ah = Ahi + (long)bz * sA;
    const __nv_bfloat16* Al = Alo + (long)bz * sA;
    const __nv_bfloat16* Bh = Bhi + (long)bz * sB;
    const __nv_bfloat16* Bl = Blo + (long)bz * sB;

    int tid = threadIdx.x, lane = tid & 31, wid = tid >> 5;
    int wm = wid & 3;                    // 4 warps along M
    int wn = wid >> 2;                   // 2 warps along N

    int kend = (MODE == 2) ? min(K, bm * 128 + 128) : K;
    int nch  = kend >> 5;                // BK=32 chunks (always >= 2 here)

    int aRow0 = bm * 128, bRow0 = bn * 128;

    float acc[2][8][4];
#pragma unroll
    for (int i = 0; i < 2; i++)
#pragma unroll
        for (int j = 0; j < 8; j++)
#pragma unroll
            for (int r = 0; r < 4; r++) acc[i][j][r] = 0.0f;

    // ldmatrix lane address components
    int arow_l = wm * 32 + (lane & 15);
    int ac_sel = lane >> 4;                            // 0/1
    int brow_l = wn * 64 + ((lane >> 4) << 3) + (lane & 7);   // NT path
    int bc_sel = (lane >> 3) & 1;
    int tk_l   = ((lane >> 3) & 1) * 8 + (lane & 7);   // trans path: k in k16
    int tcc_l  = wn * 8 + (lane >> 4);                 // trans path: n/8 chunk

    // Persistent ks1 fragments for the deferred lo*hi pass (live across sync)
    uint32_t a_lo_d[2][4], b_hi_d[4][4];

    load_tiles<BTRANS>(sbase, Ah, Al, Bh, Bl, K, N, aRow0, bRow0, 0, tid);
    CP_COMMIT();

    for (int i = 0; i < nch; i++) {
        uint32_t sb = sbase + (uint32_t)(i & 1) * 32768;
        CP_WAIT(0);                      // current stage landed
        __syncthreads();                 // visibility + WAR on rewritten buf

        if (i + 1 < nch) {
            load_tiles<BTRANS>(sbase + (uint32_t)((i + 1) & 1) * 32768,
                               Ah, Al, Bh, Bl, K, N, aRow0, bRow0, (i + 1) * 32, tid);
            CP_COMMIT();
        }

        // ---- ks0 A fragments issued FIRST: latency hides under deferred MMAs
        uint32_t a_hi[2][4], a_lo[2][4];
#pragma unroll
        for (int mt = 0; mt < 2; mt++) {
            int r = arow_l + mt * 16;
            int c = ac_sel;
            uint32_t off = (uint32_t)(r << 6) + ((uint32_t)(c ^ ((r >> 1) & 3)) << 4);
            LDSM4(a_hi[mt][0], a_hi[mt][1], a_hi[mt][2], a_hi[mt][3], sb + off);
            LDSM4(a_lo[mt][0], a_lo[mt][1], a_lo[mt][2], a_lo[mt][3], sb + 8192 + off);
        }

        // Deferred lo*hi of previous chunk's ks1 — register-only tensor work
        if (i > 0) {
#pragma unroll
            for (int mt = 0; mt < 2; mt++)
#pragma unroll
                for (int g = 0; g < 4; g++)
#pragma unroll
                    for (int h = 0; h < 2; h++)
                        MMA16816(acc[mt][g * 2 + h], a_lo_d[mt], b_hi_d[g][h * 2], b_hi_d[g][h * 2 + 1]);
        }

        // ---- ks = 0: B fragments + 3 passes ----
        {
            uint32_t b_hi[4][4], b_lo[4][4];
            if (BTRANS == 0) {
#pragma unroll
                for (int g = 0; g < 4; g++) {
                    int r = brow_l + g * 16;
                    int c = bc_sel;
                    uint32_t off = (uint32_t)(r << 6) + ((uint32_t)(c ^ ((r >> 1) & 3)) << 4);
                    LDSM4(b_hi[g][0], b_hi[g][1], b_hi[g][2], b_hi[g][3], sb + 16384 + off);
                    LDSM4(b_lo[g][0], b_lo[g][1], b_lo[g][2], b_lo[g][3], sb + 24576 + off);
                }
            } else {
#pragma unroll
                for (int g = 0; g < 4; g++) {
                    int kr = tk_l;
                    int cc = tcc_l + g * 2;
                    uint32_t off = (uint32_t)(kr << 8) + ((uint32_t)(cc ^ (kr & 7)) << 4);
                    LDSM4T(b_hi[g][0], b_hi[g][1], b_hi[g][2], b_hi[g][3], sb + 16384 + off);
                    LDSM4T(b_lo[g][0], b_lo[g][1], b_lo[g][2], b_lo[g][3], sb + 24576 + off);
                }
            }
#pragma unroll
            for (int mt = 0; mt < 2; mt++)
#pragma unroll
                for (int g = 0; g < 4; g++)
#pragma unroll
                    for (int h = 0; h < 2; h++)
                        MMA16816(acc[mt][g * 2 + h], a_hi[mt], b_hi[g][h * 2], b_hi[g][h * 2 + 1]);
#pragma unroll
            for (int mt = 0; mt < 2; mt++)
#pragma unroll
                for (int g = 0; g < 4; g++)
#pragma unroll
                    for (int h = 0; h < 2; h++)
                        MMA16816(acc[mt][g * 2 + h], a_hi[mt], b_lo[g][h * 2], b_lo[g][h * 2 + 1]);
#pragma unroll
            for (int mt = 0; mt < 2; mt++)
#pragma unroll
                for (int g = 0; g < 4; g++)
#pragma unroll
                    for (int h = 0; h < 2; h++)
                        MMA16816(acc[mt][g * 2 + h], a_lo[mt], b_hi[g][h * 2], b_hi[g][h * 2 + 1]);
        }

        // ---- ks = 1: hi*hi + hi*lo now; lo*hi (a_lo_d x b_hi_d) deferred ----
        {
            uint32_t a_hi1[2][4], b_lo[4][4];
#pragma unroll
            for (int mt = 0; mt < 2; mt++) {
                int r = arow_l + mt * 16;
                int c = 2 + ac_sel;
                uint32_t off = (uint32_t)(r << 6) + ((uint32_t)(c ^ ((r >> 1) & 3)) << 4);
                LDSM4(a_hi1[mt][0], a_hi1[mt][1], a_hi1[mt][2], a_hi1[mt][3], sb + off);
                LDSM4(a_lo_d[mt][0], a_lo_d[mt][1], a_lo_d[mt][2], a_lo_d[mt][3], sb + 8192 + off);
            }
            if (BTRANS == 0) {
#pragma unroll
                for (int g = 0; g < 4; g++) {
                    int r = brow_l + g * 16;
                    int c = 2 + bc_sel;
                    uint32_t off = (uint32_t)(r << 6) + ((uint32_t)(c ^ ((r >> 1) & 3)) << 4);
                    LDSM4(b_hi_d[g][0], b_hi_d[g][1], b_hi_d[g][2], b_hi_d[g][3], sb + 16384 + off);
                    LDSM4(b_lo[g][0], b_lo[g][1], b_lo[g][2], b_lo[g][3], sb + 24576 + off);
                }
            } else {
#pragma unroll
                for (int g = 0; g < 4; g++) {
                    int kr = 16 + tk_l;
                    int cc = tcc_l + g * 2;
                    uint32_t off = (uint32_t)(kr << 8) + ((uint32_t)(cc ^ (kr & 7)) << 4);
                    LDSM4T(b_hi_d[g][0], b_hi_d[g][1], b_hi_d[g][2], b_hi_d[g][3], sb + 16384 + off);
                    LDSM4T(b_lo[g][0], b_lo[g][1], b_lo[g][2], b_lo[g][3], sb + 24576 + off);
                }
            }
#pragma unroll
            for (int mt = 0; mt < 2; mt++)
#pragma unroll
                for (int g = 0; g < 4; g++)
#pragma unroll
                    for (int h = 0; h < 2; h++)
                        MMA16816(acc[mt][g * 2 + h], a_hi1[mt], b_hi_d[g][h * 2], b_hi_d[g][h * 2 + 1]);
#pragma unroll
            for (int mt = 0; mt < 2; mt++)
#pragma unroll
                for (int g = 0; g < 4; g++)
#pragma unroll
                    for (int h = 0; h < 2; h++)
                        MMA16816(acc[mt][g * 2 + h], a_hi1[mt], b_lo[g][h * 2], b_lo[g][h * 2 + 1]);
            // lo*hi deferred to next iteration (or flush below)
        }
    }

    // Flush the final deferred lo*hi pass
#pragma unroll
    for (int mt = 0; mt < 2; mt++)
#pragma unroll
        for (int g = 0; g < 4; g++)
#pragma unroll
            for (int h = 0; h < 2; h++)
                MMA16816(acc[mt][g * 2 + h], a_lo_d[mt], b_hi_d[g][h * 2], b_hi_d[g][h * 2 + 1]);

    // Epilogue
    int row0 = bm * 128 + wm * 32 + (lane >> 2);
    int col0 = bn * 128 + wn * 64 + (lane & 3) * 2;
    if (OUTMODE == 0) {
        float* Cb = C + (long)bz * sC;
#pragma unroll
        for (int mt = 0; mt < 2; mt++)
#pragma unroll
            for (int nt = 0; nt < 8; nt++) {
                float* p0 = Cb + (long)(row0 + mt * 16) * N + col0 + nt * 8;
                float* p1 = p0 + 8 * N;
                float2 v0 = { acc[mt][nt][0] * scale, acc[mt][nt][1] * scale };
                float2 v1 = { acc[mt][nt][2] * scale, acc[mt][nt][3] * scale };
                *(float2*)p0 = v0;
                *(float2*)p1 = v1;
            }
    } else {
        __nv_bfloat16* Hb = Chi + (long)bz * sC;
        __nv_bfloat16* Lb = Clo + (long)bz * sC;
#pragma unroll
        for (int mt = 0; mt < 2; mt++)
#pragma unroll
            for (int nt = 0; nt < 8; nt++)
#pragma unroll
                for (int hh = 0; hh < 2; hh++) {
                    long o = (long)(row0 + mt * 16 + hh * 8) * N + col0 + nt * 8;
                    float v0 = acc[mt][nt][hh * 2 + 0] * scale;
                    float v1 = acc[mt][nt][hh * 2 + 1] * scale;
                    __nv_bfloat16 h0 = __float2bfloat16(v0);
                    __nv_bfloat16 h1 = __float2bfloat16(v1);
                    *(__nv_bfloat162*)(Hb + o) = __nv_bfloat162(h0, h1);
                    *(__nv_bfloat162*)(Lb + o) =
                        __nv_bfloat162(__float2bfloat16(v0 - __bfloat162float(h0)),
                                       __float2bfloat16(v1 - __bfloat162float(h1)));
                }
    }
}

// ---------------------------------------------------------------------------
// Fused fp32 -> (hi, lo) bf16 split for x, Wk, Wv in ONE launch.
// ---------------------------------------------------------------------------
__device__ __forceinline__ void split4(const float* __restrict__ s,
                                       __nv_bfloat16* __restrict__ hi,
                                       __nv_bfloat16* __restrict__ lo, long i)
{
    float4 v = *(const float4*)(s + i);
    __nv_bfloat16 h0 = __float2bfloat16(v.x), h1 = __float2bfloat16(v.y);
    __nv_bfloat16 h2 = __float2bfloat16(v.z), h3 = __float2bfloat16(v.w);
    __nv_bfloat162* H = (__nv_bfloat162*)(hi + i);
    H[0] = __nv_bfloat162(h0, h1);
    H[1] = __nv_bfloat162(h2, h3);
    __nv_bfloat162* L = (__nv_bfloat162*)(lo + i);
    L[0] = __nv_bfloat162(__float2bfloat16(v.x - __bfloat162float(h0)),
                          __float2bfloat16(v.y - __bfloat162float(h1)));
    L[1] = __nv_bfloat162(__float2bfloat16(v.z - __bfloat162float(h2)),
                          __float2bfloat16(v.w - __bfloat162float(h3)));
}

__global__ void __launch_bounds__(256) split_all_kernel(
    const float* __restrict__ x,  __nv_bfloat16* __restrict__ xhi,  __nv_bfloat16* __restrict__ xlo,
    const float* __restrict__ wk, __nv_bfloat16* __restrict__ wkhi, __nv_bfloat16* __restrict__ wklo,
    const float* __restrict__ wv, __nv_bfloat16* __restrict__ wvhi, __nv_bfloat16* __restrict__ wvlo)
{
    int bx = blockIdx.x;
    if (bx < 8192) {
        long i = ((long)bx * 256 + threadIdx.x) * 4;
        split4(x, xhi, xlo, i);
    } else if (bx < 9216) {
        long i = ((long)(bx - 8192) * 256 + threadIdx.x) * 4;
        split4(wk, wkhi, wklo, i);
    } else {
        long i = ((long)(bx - 9216) * 256 + threadIdx.x) * 4;
        split4(wv, wvhi, wvlo, i);
    }
}

// ---------------------------------------------------------------------------
// Causal softmax over S rows -> P hi/lo, single gmem read via smem row cache.
// R14: zero-fill only to the 128-boundary (= PV kend for this row); the PV
// GEMM never reads past roundup(q+1, 128), so the rest of the tail is dead.
// ---------------------------------------------------------------------------
__global__ void __launch_bounds__(256) softmax_split_kernel(
    const float* __restrict__ S, __nv_bfloat16* __restrict__ Phi,
    __nv_bfloat16* __restrict__ Plo)
{
    __shared__ float rowbuf[TT];
    __shared__ float red[8];
    int r = blockIdx.x;
    int b = r >> 11, q = r & (TT - 1);
    const float* row = S + ((long)b * TT + q) * TT;
    __nv_bfloat16* ph = Phi + ((long)b * TT + q) * TT;
    __nv_bfloat16* pl = Plo + ((long)b * TT + q) * TT;
    int L = q + 1;
    int Lpad = (q & ~127) + 128;         // PV reads only [0, Lpad)
    int tid = threadIdx.x, lane = tid & 31, wid = tid >> 5;

    float m = -INFINITY;
    int L4 = L & ~3;
    for (int j = tid * 4; j < L4; j += 1024) {
        float4 v = *(const float4*)(row + j);
        *(float4*)(rowbuf + j) = v;
        m = fmaxf(m, fmaxf(fmaxf(v.x, v.y), fmaxf(v.z, v.w)));
    }
    for (int j = L4 + tid; j < L; j += 256) {
        float v = row[j];
        rowbuf[j] = v;
        m = fmaxf(m, v);
    }
#pragma unroll
    for (int o = 16; o; o >>= 1) m = fmaxf(m, __shfl_xor_sync(0xffffffffu, m, o));
    if (lane == 0) red[wid] = m;
    __syncthreads();
    if (tid == 0) {
        float mx = red[0];
#pragma unroll
        for (int i = 1; i < 8; i++) mx = fmaxf(mx, red[i]);
        red[0] = mx;
    }
    __syncthreads();
    m = red[0];
    __syncthreads();

    float s = 0.0f;
    for (int j = tid; j < L; j += 256) {
        float e = __expf(rowbuf[j] - m);
        rowbuf[j] = e;
        s += e;
    }
#pragma unroll
    for (int o = 16; o; o >>= 1) s += __shfl_xor_sync(0xffffffffu, s, o);
    if (lane == 0) red[wid] = s;
    __syncthreads();
    if (tid == 0) {
        float ss = red[0];
#pragma unroll
        for (int i = 1; i < 8; i++) ss += red[i];
        red[0] = ss;
    }
    __syncthreads();
    float inv = 1.0f / red[0];

    for (int j = tid; j < L; j += 256) {
        float e = rowbuf[j] * inv;
        __nv_bfloat16 hv = __float2bfloat16(e);
        ph[j] = hv;
        pl[j] = __float2bfloat16(e - __bfloat162float(hv));
    }
    __nv_bfloat16 z = __float2bfloat16(0.0f);
    for (int j = L + tid; j < Lpad; j += 256) { ph[j] = z; pl[j] = z; }
}

// ---------------------------------------------------------------------------
// Launch
// ---------------------------------------------------------------------------
extern "C" void kernel_launch(void* const* d_in, const int* in_sizes, int n_in,
                              void* d_out, int out_size)
{
    const float* x  = (const float*)d_in[0];   // [B,T,C]
    const float* Wk = (const float*)d_in[1];   // [H,C]
    const float* Wv = (const float*)d_in[2];   // [H,C]
    float* out = (float*)d_out;                // [B,T,H]

    __nv_bfloat16 *xhi, *xlo, *wkhi, *wklo, *wvhi, *wvlo;
    __nv_bfloat16 *khi, *klo, *vhi, *vlo, *phi, *plo;
    float *sp;
    cudaGetSymbolAddress((void**)&xhi,  g_xhi);
    cudaGetSymbolAddress((void**)&xlo,  g_xlo);
    cudaGetSymbolAddress((void**)&wkhi, g_wkhi);
    cudaGetSymbolAddress((void**)&wklo, g_wklo);
    cudaGetSymbolAddress((void**)&wvhi, g_wvhi);
    cudaGetSymbolAddress((void**)&wvlo, g_wvlo);
    cudaGetSymbolAddress((void**)&khi,  g_Khi);
    cudaGetSymbolAddress((void**)&klo,  g_Klo);
    cudaGetSymbolAddress((void**)&vhi,  g_Vhi);
    cudaGetSymbolAddress((void**)&vlo,  g_Vlo);
    cudaGetSymbolAddress((void**)&sp,   g_S);
    cudaGetSymbolAddress((void**)&phi,  g_Phi);
    cudaGetSymbolAddress((void**)&plo,  g_Plo);

    cudaFuncSetAttribute(mma_gemm<3, 1, 0>, cudaFuncAttributeMaxDynamicSharedMemorySize,
                         GEMM_SMEM_BYTES);
    cudaFuncSetAttribute(mma_gemm<1, 0, 0>, cudaFuncAttributeMaxDynamicSharedMemorySize,
                         GEMM_SMEM_BYTES);
    cudaFuncSetAttribute(mma_gemm<2, 0, 1>, cudaFuncAttributeMaxDynamicSharedMemorySize,
                         GEMM_SMEM_BYTES);

    const float scale = 1.0f / 32.0f;          // HEAD_SIZE^-0.5

    // 1) split x, Wk, Wv into bf16 hi/lo — single fused launch
    split_all_kernel<<<10240, 256>>>(x, xhi, xlo, Wk, wkhi, wklo, Wv, wvhi, wvlo);

    // 2) fused K+V projections (grid.z selects weight/output pair), with
    //    bf16 hi/lo split epilogues. (q == k per the reference's bug.)
    {
        dim3 grid(HH / 128, (BB * TT) / 128, 2);
        mma_gemm<3, 1, 0><<<grid, 256, GEMM_SMEM_BYTES>>>(
            xhi, xlo, wkhi, wklo, wvhi, wvlo,
            nullptr, khi, klo, vhi, vlo,
            BB * TT, HH, CC, 0, 0, 0, 1.0f);
    }

    // 3) S = scale * K @ K^T, lower-triangular tiles only (triangular grid)
    {
        int tm = TT / 128;
        dim3 grid(tm * (tm + 1) / 2, 1, BB);
        mma_gemm<1, 0, 0><<<grid, 256, GEMM_SMEM_BYTES>>>(
            khi, klo, khi, klo, nullptr, nullptr,
            sp, nullptr, nullptr, nullptr, nullptr,
            TT, TT, HH, (long)TT * HH, (long)TT * HH, (long)TT * TT, scale);
    }

    // 4) causal softmax -> P hi/lo (smem row cache, 128-boundary zero-fill)
    softmax_split_kernel<<<BB * TT, 256>>>(sp, phi, plo);

    // 5) out = P @ V: V consumed in natural [t][h] layout via ldmatrix.trans,
    //    k-loop bounded by causality, longest tiles first.
    {
        dim3 grid(HH / 128, TT / 128, BB);
        mma_gemm<2, 0, 1><<<grid, 256, GEMM_SMEM_BYTES>>>(
            phi, plo, vhi, vlo, nullptr, nullptr,
            out, nullptr, nullptr, nullptr, nullptr,
            TT, HH, TT, (long)TT * TT, (long)TT * HH, (long)TT * HH, 1.0f);
    }
}

// round 16
// speedup vs baseline: 1.0225x; 1.0225x over previous
#include <cuda_runtime.h>
#include <cuda_bf16.h>
#include <cstdint>
#include <math.h>

// Problem shape (fixed by the reference)
#define BB 4
#define TT 2048
#define CC 1024
#define HH 1024

// ---------------------------------------------------------------------------
// Scratch (__device__ globals; allocation-free per harness rules)
// ---------------------------------------------------------------------------
__device__ __nv_bfloat16 g_xhi[(long)BB * TT * CC];
__device__ __nv_bfloat16 g_xlo[(long)BB * TT * CC];
__device__ __nv_bfloat16 g_wkhi[(long)HH * CC];
__device__ __nv_bfloat16 g_wklo[(long)HH * CC];
__device__ __nv_bfloat16 g_wvhi[(long)HH * CC];
__device__ __nv_bfloat16 g_wvlo[(long)HH * CC];
__device__ __nv_bfloat16 g_Khi[(long)BB * TT * HH];
__device__ __nv_bfloat16 g_Klo[(long)BB * TT * HH];
__device__ __nv_bfloat16 g_Vhi[(long)BB * TT * HH];   // natural [b][t][h]
__device__ __nv_bfloat16 g_Vlo[(long)BB * TT * HH];
__device__ float         g_S[(long)BB * TT * TT];
__device__ __nv_bfloat16 g_Phi[(long)BB * TT * TT];
__device__ __nv_bfloat16 g_Plo[(long)BB * TT * TT];

// ---------------------------------------------------------------------------
// PTX helpers (compute_103-safe: sm_80-era tensor ISA only)
// ---------------------------------------------------------------------------
__device__ __forceinline__ uint32_t smem_u32(const void* p) {
    uint32_t a;
    asm("{ .reg .u64 t; cvta.to.shared.u64 t, %1; cvt.u32.u64 %0, t; }"
        : "=r"(a) : "l"(p));
    return a;
}

__device__ __forceinline__ void cpa16(uint32_t s, const void* g) {
    asm volatile("cp.async.cg.shared.global [%0], [%1], 16;" :: "r"(s), "l"(g));
}
#define CP_COMMIT()  asm volatile("cp.async.commit_group;" ::: "memory")
#define CP_WAIT(n)   asm volatile("cp.async.wait_group %0;" :: "n"(n) : "memory")

#define LDSM4(r0, r1, r2, r3, addr) \
    asm volatile("ldmatrix.sync.aligned.m8n8.x4.shared.b16 {%0,%1,%2,%3}, [%4];" \
                 : "=r"(r0), "=r"(r1), "=r"(r2), "=r"(r3) : "r"(addr))

#define LDSM4T(r0, r1, r2, r3, addr) \
    asm volatile("ldmatrix.sync.aligned.m8n8.x4.trans.shared.b16 {%0,%1,%2,%3}, [%4];" \
                 : "=r"(r0), "=r"(r1), "=r"(r2), "=r"(r3) : "r"(addr))

#define MMA16816(c, a, b0, b1) \
    asm volatile("mma.sync.aligned.m16n8k16.row.col.f32.bf16.bf16.f32 " \
                 "{%0,%1,%2,%3}, {%4,%5,%6,%7}, {%8,%9}, {%0,%1,%2,%3};" \
                 : "+f"((c)[0]), "+f"((c)[1]), "+f"((c)[2]), "+f"((c)[3]) \
                 : "r"((a)[0]), "r"((a)[1]), "r"((a)[2]), "r"((a)[3]), \
                   "r"(b0), "r"(b1))

// ---------------------------------------------------------------------------
// HMMA GEMM, bf16x3 split precision, 2-stage cp.async pipeline.
// R13 structure EXACTLY (measured best: 549.6us): cross-boundary deferral of
// ks1's lo*hi pass; deferred MMAs issued first after sync, THEN ks0 loads.
// (R14's A-LDSM hoist above the deferred pass regressed ~10us — reverted.)
// Per-accumulator MMA order: hi*hi, hi*lo, lo*hi per ks -> stable numerics.
// MODE: 1 = causal triangular decode, 2 = k-bounded PV (bm reversed),
//       3 = fused dual projection (blockIdx.z selects B/C set)
// OUTMODE: 0 = fp32 C (scaled); 1 = bf16 hi/lo split into Chi/Clo
// BTRANS:  0 = B [n][k] NT; 1 = B [k][n] via ldmatrix.trans
// ---------------------------------------------------------------------------
#define GEMM_SMEM_BYTES (2 * 32768)

template <int BTRANS>
__device__ __forceinline__ void load_tiles(
    uint32_t sb, const __nv_bfloat16* __restrict__ Ah,
    const __nv_bfloat16* __restrict__ Al,
    const __nv_bfloat16* __restrict__ Bh,
    const __nv_bfloat16* __restrict__ Bl,
    int K, int N, int aRow0, int bRow0, int kh, int tid)
{
#pragma unroll
    for (int t = 0; t < 2; t++) {
        int idx = tid + t * 256;
        int row = idx >> 2;              // 0..127
        int c   = idx & 3;
        uint32_t off = (uint32_t)(row << 6) + ((uint32_t)(c ^ ((row >> 1) & 3)) << 4);
        long ga = (long)(aRow0 + row) * K + kh + c * 8;
        cpa16(sb + off,        Ah + ga);
        cpa16(sb + 8192 + off, Al + ga);
    }
    if (BTRANS == 0) {
#pragma unroll
        for (int t = 0; t < 2; t++) {
            int idx = tid + t * 256;
            int row = idx >> 2;
            int c   = idx & 3;
            uint32_t off = (uint32_t)(row << 6) + ((uint32_t)(c ^ ((row >> 1) & 3)) << 4);
            long gb = (long)(bRow0 + row) * K + kh + c * 8;
            cpa16(sb + 16384 + off, Bh + gb);
            cpa16(sb + 24576 + off, Bl + gb);
        }
    } else {
#pragma unroll
        for (int t = 0; t < 2; t++) {
            int idx = tid + t * 256;
            int row = idx >> 4;          // 0..31 (k)
            int c   = idx & 15;          // 16B chunk (8 n)
            uint32_t off = (uint32_t)(row << 8) + ((uint32_t)(c ^ (row & 7)) << 4);
            long gb = (long)(kh + row) * N + bRow0 + c * 8;
            cpa16(sb + 16384 + off, Bh + gb);
            cpa16(sb + 24576 + off, Bl + gb);
        }
    }
}

template <int MODE, int OUTMODE, int BTRANS>
__global__ void __launch_bounds__(256, 2)
mma_gemm(const __nv_bfloat16* __restrict__ Ahi, const __nv_bfloat16* __restrict__ Alo,
         const __nv_bfloat16* __restrict__ Bhi, const __nv_bfloat16* __restrict__ Blo,
         const __nv_bfloat16* __restrict__ Bhi2, const __nv_bfloat16* __restrict__ Blo2,
         float* __restrict__ C,
         __nv_bfloat16* __restrict__ Chi, __nv_bfloat16* __restrict__ Clo,
         __nv_bfloat16* __restrict__ Chi2, __nv_bfloat16* __restrict__ Clo2,
         int M, int N, int K, long sA, long sB, long sC, float scale)
{
    int bm, bn, bz;
    if (MODE == 1) {
        int i = blockIdx.x;
        bm = (int)((sqrtf(8.0f * (float)i + 1.0f) - 1.0f) * 0.5f);
        while ((bm + 1) * (bm + 2) / 2 <= i) bm++;
        while (bm * (bm + 1) / 2 > i) bm--;
        bn = i - bm * (bm + 1) / 2;
        bz = blockIdx.z;
    } else if (MODE == 3) {
        bm = blockIdx.y; bn = blockIdx.x; bz = 0;
        if (blockIdx.z) { Bhi = Bhi2; Blo = Blo2; Chi = Chi2; Clo = Clo2; }
    } else {
        bm = blockIdx.y; bn = blockIdx.x; bz = blockIdx.z;
        if (MODE == 2) bm = gridDim.y - 1 - bm;   // longest-k tiles first
    }

    extern __shared__ __align__(1024) char smem[];
    uint32_t sbase = smem_u32(smem);

    const __nv_bfloat16* Ah = Ahi + (long)bz * sA;
    const __nv_bfloat16* Al = Alo + (long)bz * sA;
    const __nv_bfloat16* Bh = Bhi + (long)bz * sB;
    const __nv_bfloat16* Bl = Blo + (long)bz * sB;

    int tid = threadIdx.x, lane = tid & 31, wid = tid >> 5;
    int wm = wid & 3;                    // 4 warps along M
    int wn = wid >> 2;                   // 2 warps along N

    int kend = (MODE == 2) ? min(K, bm * 128 + 128) : K;
    int nch  = kend >> 5;                // BK=32 chunks (always >= 2 here)

    int aRow0 = bm * 128, bRow0 = bn * 128;

    float acc[2][8][4];
#pragma unroll
    for (int i = 0; i < 2; i++)
#pragma unroll
        for (int j = 0; j < 8; j++)
#pragma unroll
            for (int r = 0; r < 4; r++) acc[i][j][r] = 0.0f;

    // ldmatrix lane address components
    int arow_l = wm * 32 + (lane & 15);
    int ac_sel = lane >> 4;                            // 0/1
    int brow_l = wn * 64 + ((lane >> 4) << 3) + (lane & 7);   // NT path
    int bc_sel = (lane >> 3) & 1;
    int tk_l   = ((lane >> 3) & 1) * 8 + (lane & 7);   // trans path: k in k16
    int tcc_l  = wn * 8 + (lane >> 4);                 // trans path: n/8 chunk

    // Persistent ks1 fragments for the deferred lo*hi pass (live across sync)
    uint32_t a_lo_d[2][4], b_hi_d[4][4];

    load_tiles<BTRANS>(sbase, Ah, Al, Bh, Bl, K, N, aRow0, bRow0, 0, tid);
    CP_COMMIT();

    for (int i = 0; i < nch; i++) {
        uint32_t sb = sbase + (uint32_t)(i & 1) * 32768;
        CP_WAIT(0);                      // current stage landed
        __syncthreads();                 // visibility + WAR on rewritten buf

        if (i + 1 < nch) {
            load_tiles<BTRANS>(sbase + (uint32_t)((i + 1) & 1) * 32768,
                               Ah, Al, Bh, Bl, K, N, aRow0, bRow0, (i + 1) * 32, tid);
            CP_COMMIT();
        }

        // Deferred lo*hi of previous chunk's ks1 — register-only tensor work
        // that keeps the pipe fed through the sync/LDSM window.
        if (i > 0) {
#pragma unroll
            for (int mt = 0; mt < 2; mt++)
#pragma unroll
                for (int g = 0; g < 4; g++)
#pragma unroll
                    for (int h = 0; h < 2; h++)
                        MMA16816(acc[mt][g * 2 + h], a_lo_d[mt], b_hi_d[g][h * 2], b_hi_d[g][h * 2 + 1]);
        }

        // ---- ks = 0: full 3 passes from locals ----
        {
            uint32_t a_hi[2][4], a_lo[2][4], b_hi[4][4], b_lo[4][4];
#pragma unroll
            for (int mt = 0; mt < 2; mt++) {
                int r = arow_l + mt * 16;
                int c = ac_sel;
                uint32_t off = (uint32_t)(r << 6) + ((uint32_t)(c ^ ((r >> 1) & 3)) << 4);
                LDSM4(a_hi[mt][0], a_hi[mt][1], a_hi[mt][2], a_hi[mt][3], sb + off);
                LDSM4(a_lo[mt][0], a_lo[mt][1], a_lo[mt][2], a_lo[mt][3], sb + 8192 + off);
            }
            if (BTRANS == 0) {
#pragma unroll
                for (int g = 0; g < 4; g++) {
                    int r = brow_l + g * 16;
                    int c = bc_sel;
                    uint32_t off = (uint32_t)(r << 6) + ((uint32_t)(c ^ ((r >> 1) & 3)) << 4);
                    LDSM4(b_hi[g][0], b_hi[g][1], b_hi[g][2], b_hi[g][3], sb + 16384 + off);
                    LDSM4(b_lo[g][0], b_lo[g][1], b_lo[g][2], b_lo[g][3], sb + 24576 + off);
                }
            } else {
#pragma unroll
                for (int g = 0; g < 4; g++) {
                    int kr = tk_l;
                    int cc = tcc_l + g * 2;
                    uint32_t off = (uint32_t)(kr << 8) + ((uint32_t)(cc ^ (kr & 7)) << 4);
                    LDSM4T(b_hi[g][0], b_hi[g][1], b_hi[g][2], b_hi[g][3], sb + 16384 + off);
                    LDSM4T(b_lo[g][0], b_lo[g][1], b_lo[g][2], b_lo[g][3], sb + 24576 + off);
                }
            }
#pragma unroll
            for (int mt = 0; mt < 2; mt++)
#pragma unroll
                for (int g = 0; g < 4; g++)
#pragma unroll
                    for (int h = 0; h < 2; h++)
                        MMA16816(acc[mt][g * 2 + h], a_hi[mt], b_hi[g][h * 2], b_hi[g][h * 2 + 1]);
#pragma unroll
            for (int mt = 0; mt < 2; mt++)
#pragma unroll
                for (int g = 0; g < 4; g++)
#pragma unroll
                    for (int h = 0; h < 2; h++)
                        MMA16816(acc[mt][g * 2 + h], a_hi[mt], b_lo[g][h * 2], b_lo[g][h * 2 + 1]);
#pragma unroll
            for (int mt = 0; mt < 2; mt++)
#pragma unroll
                for (int g = 0; g < 4; g++)
#pragma unroll
                    for (int h = 0; h < 2; h++)
                        MMA16816(acc[mt][g * 2 + h], a_lo[mt], b_hi[g][h * 2], b_hi[g][h * 2 + 1]);
        }

        // ---- ks = 1: hi*hi + hi*lo now; lo*hi (a_lo_d x b_hi_d) deferred ----
        {
            uint32_t a_hi[2][4], b_lo[4][4];
#pragma unroll
            for (int mt = 0; mt < 2; mt++) {
                int r = arow_l + mt * 16;
                int c = 2 + ac_sel;
                uint32_t off = (uint32_t)(r << 6) + ((uint32_t)(c ^ ((r >> 1) & 3)) << 4);
                LDSM4(a_hi[mt][0], a_hi[mt][1], a_hi[mt][2], a_hi[mt][3], sb + off);
                LDSM4(a_lo_d[mt][0], a_lo_d[mt][1], a_lo_d[mt][2], a_lo_d[mt][3], sb + 8192 + off);
            }
            if (BTRANS == 0) {
#pragma unroll
                for (int g = 0; g < 4; g++) {
                    int r = brow_l + g * 16;
                    int c = 2 + bc_sel;
                    uint32_t off = (uint32_t)(r << 6) + ((uint32_t)(c ^ ((r >> 1) & 3)) << 4);
                    LDSM4(b_hi_d[g][0], b_hi_d[g][1], b_hi_d[g][2], b_hi_d[g][3], sb + 16384 + off);
                    LDSM4(b_lo[g][0], b_lo[g][1], b_lo[g][2], b_lo[g][3], sb + 24576 + off);
                }
            } else {
#pragma unroll
                for (int g = 0; g < 4; g++) {
                    int kr = 16 + tk_l;
                    int cc = tcc_l + g * 2;
                    uint32_t off = (uint32_t)(kr << 8) + ((uint32_t)(cc ^ (kr & 7)) << 4);
                    LDSM4T(b_hi_d[g][0], b_hi_d[g][1], b_hi_d[g][2], b_hi_d[g][3], sb + 16384 + off);
                    LDSM4T(b_lo[g][0], b_lo[g][1], b_lo[g][2], b_lo[g][3], sb + 24576 + off);
                }
            }
#pragma unroll
            for (int mt = 0; mt < 2; mt++)
#pragma unroll
                for (int g = 0; g < 4; g++)
#pragma unroll
                    for (int h = 0; h < 2; h++)
                        MMA16816(acc[mt][g * 2 + h], a_hi[mt], b_hi_d[g][h * 2], b_hi_d[g][h * 2 + 1]);
#pragma unroll
            for (int mt = 0; mt < 2; mt++)
#pragma unroll
                for (int g = 0; g < 4; g++)
#pragma unroll
                    for (int h = 0; h < 2; h++)
                        MMA16816(acc[mt][g * 2 + h], a_hi[mt], b_lo[g][h * 2], b_lo[g][h * 2 + 1]);
            // lo*hi deferred to next iteration (or flush below)
        }
    }

    // Flush the final deferred lo*hi pass
#pragma unroll
    for (int mt = 0; mt < 2; mt++)
#pragma unroll
        for (int g = 0; g < 4; g++)
#pragma unroll
            for (int h = 0; h < 2; h++)
                MMA16816(acc[mt][g * 2 + h], a_lo_d[mt], b_hi_d[g][h * 2], b_hi_d[g][h * 2 + 1]);

    // Epilogue
    int row0 = bm * 128 + wm * 32 + (lane >> 2);
    int col0 = bn * 128 + wn * 64 + (lane & 3) * 2;
    if (OUTMODE == 0) {
        float* Cb = C + (long)bz * sC;
#pragma unroll
        for (int mt = 0; mt < 2; mt++)
#pragma unroll
            for (int nt = 0; nt < 8; nt++) {
                float* p0 = Cb + (long)(row0 + mt * 16) * N + col0 + nt * 8;
                float* p1 = p0 + 8 * N;
                float2 v0 = { acc[mt][nt][0] * scale, acc[mt][nt][1] * scale };
                float2 v1 = { acc[mt][nt][2] * scale, acc[mt][nt][3] * scale };
                *(float2*)p0 = v0;
                *(float2*)p1 = v1;
            }
    } else {
        __nv_bfloat16* Hb = Chi + (long)bz * sC;
        __nv_bfloat16* Lb = Clo + (long)bz * sC;
#pragma unroll
        for (int mt = 0; mt < 2; mt++)
#pragma unroll
            for (int nt = 0; nt < 8; nt++)
#pragma unroll
                for (int hh = 0; hh < 2; hh++) {
                    long o = (long)(row0 + mt * 16 + hh * 8) * N + col0 + nt * 8;
                    float v0 = acc[mt][nt][hh * 2 + 0] * scale;
                    float v1 = acc[mt][nt][hh * 2 + 1] * scale;
                    __nv_bfloat16 h0 = __float2bfloat16(v0);
                    __nv_bfloat16 h1 = __float2bfloat16(v1);
                    *(__nv_bfloat162*)(Hb + o) = __nv_bfloat162(h0, h1);
                    *(__nv_bfloat162*)(Lb + o) =
                        __nv_bfloat162(__float2bfloat16(v0 - __bfloat162float(h0)),
                                       __float2bfloat16(v1 - __bfloat162float(h1)));
                }
    }
}

// ---------------------------------------------------------------------------
// Fused fp32 -> (hi, lo) bf16 split for x, Wk, Wv in ONE launch.
// ---------------------------------------------------------------------------
__device__ __forceinline__ void split4(const float* __restrict__ s,
                                       __nv_bfloat16* __restrict__ hi,
                                       __nv_bfloat16* __restrict__ lo, long i)
{
    float4 v = *(const float4*)(s + i);
    __nv_bfloat16 h0 = __float2bfloat16(v.x), h1 = __float2bfloat16(v.y);
    __nv_bfloat16 h2 = __float2bfloat16(v.z), h3 = __float2bfloat16(v.w);
    __nv_bfloat162* H = (__nv_bfloat162*)(hi + i);
    H[0] = __nv_bfloat162(h0, h1);
    H[1] = __nv_bfloat162(h2, h3);
    __nv_bfloat162* L = (__nv_bfloat162*)(lo + i);
    L[0] = __nv_bfloat162(__float2bfloat16(v.x - __bfloat162float(h0)),
                          __float2bfloat16(v.y - __bfloat162float(h1)));
    L[1] = __nv_bfloat162(__float2bfloat16(v.z - __bfloat162float(h2)),
                          __float2bfloat16(v.w - __bfloat162float(h3)));
}

__global__ void __launch_bounds__(256) split_all_kernel(
    const float* __restrict__ x,  __nv_bfloat16* __restrict__ xhi,  __nv_bfloat16* __restrict__ xlo,
    const float* __restrict__ wk, __nv_bfloat16* __restrict__ wkhi, __nv_bfloat16* __restrict__ wklo,
    const float* __restrict__ wv, __nv_bfloat16* __restrict__ wvhi, __nv_bfloat16* __restrict__ wvlo)
{
    int bx = blockIdx.x;
    if (bx < 8192) {
        long i = ((long)bx * 256 + threadIdx.x) * 4;
        split4(x, xhi, xlo, i);
    } else if (bx < 9216) {
        long i = ((long)(bx - 8192) * 256 + threadIdx.x) * 4;
        split4(wk, wkhi, wklo, i);
    } else {
        long i = ((long)(bx - 9216) * 256 + threadIdx.x) * 4;
        split4(wv, wvhi, wvlo, i);
    }
}

// ---------------------------------------------------------------------------
// Causal softmax over S rows -> P hi/lo. Issue-bound, so all hot loops are
// 4-wide vectorized (float4 smem ops, bf16x2 paired stores). Zero-fill only
// to the 128-boundary (PV kend). Single gmem read via smem row cache.
// ---------------------------------------------------------------------------
__global__ void __launch_bounds__(256) softmax_split_kernel(
    const float* __restrict__ S, __nv_bfloat16* __restrict__ Phi,
    __nv_bfloat16* __restrict__ Plo)
{
    __shared__ float rowbuf[TT];
    __shared__ float red[8];
    int r = blockIdx.x;
    int b = r >> 11, q = r & (TT - 1);
    const float* row = S + ((long)b * TT + q) * TT;
    __nv_bfloat16* ph = Phi + ((long)b * TT + q) * TT;
    __nv_bfloat16* pl = Plo + ((long)b * TT + q) * TT;
    int L = q + 1;
    int Lpad = (q & ~127) + 128;         // PV reads only [0, Lpad)
    int tid = threadIdx.x, lane = tid & 31, wid = tid >> 5;
    int L4 = L & ~3;

    // 1) load row into smem (float4), tracking max
    float m = -INFINITY;
    for (int j = tid * 4; j < L4; j += 1024) {
        float4 v = *(const float4*)(row + j);
        *(float4*)(rowbuf + j) = v;
        m = fmaxf(m, fmaxf(fmaxf(v.x, v.y), fmaxf(v.z, v.w)));
    }
    for (int j = L4 + tid; j < L; j += 256) {
        float v = row[j];
        rowbuf[j] = v;
        m = fmaxf(m, v);
    }
#pragma unroll
    for (int o = 16; o; o >>= 1) m = fmaxf(m, __shfl_xor_sync(0xffffffffu, m, o));
    if (lane == 0) red[wid] = m;
    __syncthreads();
    if (tid == 0) {
        float mx = red[0];
#pragma unroll
        for (int i = 1; i < 8; i++) mx = fmaxf(mx, red[i]);
        red[0] = mx;
    }
    __syncthreads();
    m = red[0];
    __syncthreads();

    // 2) exp in smem + sum (float4)
    float s = 0.0f;
    for (int j = tid * 4; j < L4; j += 1024) {
        float4 v = *(const float4*)(rowbuf + j);
        v.x = __expf(v.x - m); v.y = __expf(v.y - m);
        v.z = __expf(v.z - m); v.w = __expf(v.w - m);
        *(float4*)(rowbuf + j) = v;
        s += (v.x + v.y) + (v.z + v.w);
    }
    for (int j = L4 + tid; j < L; j += 256) {
        float e = __expf(rowbuf[j] - m);
        rowbuf[j] = e;
        s += e;
    }
#pragma unroll
    for (int o = 16; o; o >>= 1) s += __shfl_xor_sync(0xffffffffu, s, o);
    if (lane == 0) red[wid] = s;
    __syncthreads();
    if (tid == 0) {
        float ss = red[0];
#pragma unroll
        for (int i = 1; i < 8; i++) ss += red[i];
        red[0] = ss;
    }
    __syncthreads();
    float inv = 1.0f / red[0];

    // 3) normalize + split to bf16 hi/lo (4-wide, paired bf16x2 stores)
    for (int j = tid * 4; j < L4; j += 1024) {
        float4 v = *(const float4*)(rowbuf + j);
        float e0 = v.x * inv, e1 = v.y * inv, e2 = v.z * inv, e3 = v.w * inv;
        __nv_bfloat16 h0 = __float2bfloat16(e0), h1 = __float2bfloat16(e1);
        __nv_bfloat16 h2 = __float2bfloat16(e2), h3 = __float2bfloat16(e3);
        __nv_bfloat162* H = (__nv_bfloat162*)(ph + j);
        H[0] = __nv_bfloat162(h0, h1);
        H[1] = __nv_bfloat162(h2, h3);
        __nv_bfloat162* Lo = (__nv_bfloat162*)(pl + j);
        Lo[0] = __nv_bfloat162(__float2bfloat16(e0 - __bfloat162float(h0)),
                               __float2bfloat16(e1 - __bfloat162float(h1)));
        Lo[1] = __nv_bfloat162(__float2bfloat16(e2 - __bfloat162float(h2)),
                               __float2bfloat16(e3 - __bfloat162float(h3)));
    }
    for (int j = L4 + tid; j < L; j += 256) {
        float e = rowbuf[j] * inv;
        __nv_bfloat16 hv = __float2bfloat16(e);
        ph[j] = hv;
        pl[j] = __float2bfloat16(e - __bfloat162float(hv));
    }
    __nv_bfloat16 z = __float2bfloat16(0.0f);
    for (int j = L + tid; j < Lpad; j += 256) { ph[j] = z; pl[j] = z; }
}

// ---------------------------------------------------------------------------
// Launch
// ---------------------------------------------------------------------------
extern "C" void kernel_launch(void* const* d_in, const int* in_sizes, int n_in,
                              void* d_out, int out_size)
{
    const float* x  = (const float*)d_in[0];   // [B,T,C]
    const float* Wk = (const float*)d_in[1];   // [H,C]
    const float* Wv = (const float*)d_in[2];   // [H,C]
    float* out = (float*)d_out;                // [B,T,H]

    __nv_bfloat16 *xhi, *xlo, *wkhi, *wklo, *wvhi, *wvlo;
    __nv_bfloat16 *khi, *klo, *vhi, *vlo, *phi, *plo;
    float *sp;
    cudaGetSymbolAddress((void**)&xhi,  g_xhi);
    cudaGetSymbolAddress((void**)&xlo,  g_xlo);
    cudaGetSymbolAddress((void**)&wkhi, g_wkhi);
    cudaGetSymbolAddress((void**)&wklo, g_wklo);
    cudaGetSymbolAddress((void**)&wvhi, g_wvhi);
    cudaGetSymbolAddress((void**)&wvlo, g_wvlo);
    cudaGetSymbolAddress((void**)&khi,  g_Khi);
    cudaGetSymbolAddress((void**)&klo,  g_Klo);
    cudaGetSymbolAddress((void**)&vhi,  g_Vhi);
    cudaGetSymbolAddress((void**)&vlo,  g_Vlo);
    cudaGetSymbolAddress((void**)&sp,   g_S);
    cudaGetSymbolAddress((void**)&phi,  g_Phi);
    cudaGetSymbolAddress((void**)&plo,  g_Plo);

    cudaFuncSetAttribute(mma_gemm<3, 1, 0>, cudaFuncAttributeMaxDynamicSharedMemorySize,
                         GEMM_SMEM_BYTES);
    cudaFuncSetAttribute(mma_gemm<1, 0, 0>, cudaFuncAttributeMaxDynamicSharedMemorySize,
                         GEMM_SMEM_BYTES);
    cudaFuncSetAttribute(mma_gemm<2, 0, 1>, cudaFuncAttributeMaxDynamicSharedMemorySize,
                         GEMM_SMEM_BYTES);

    const float scale = 1.0f / 32.0f;          // HEAD_SIZE^-0.5

    // 1) split x, Wk, Wv into bf16 hi/lo — single fused launch
    split_all_kernel<<<10240, 256>>>(x, xhi, xlo, Wk, wkhi, wklo, Wv, wvhi, wvlo);

    // 2) fused K+V projections (grid.z selects weight/output pair), with
    //    bf16 hi/lo split epilogues. (q == k per the reference's bug.)
    {
        dim3 grid(HH / 128, (BB * TT) / 128, 2);
        mma_gemm<3, 1, 0><<<grid, 256, GEMM_SMEM_BYTES>>>(
            xhi, xlo, wkhi, wklo, wvhi, wvlo,
            nullptr, khi, klo, vhi, vlo,
            BB * TT, HH, CC, 0, 0, 0, 1.0f);
    }

    // 3) S = scale * K @ K^T, lower-triangular tiles only (triangular grid)
    {
        int tm = TT / 128;
        dim3 grid(tm * (tm + 1) / 2, 1, BB);
        mma_gemm<1, 0, 0><<<grid, 256, GEMM_SMEM_BYTES>>>(
            khi, klo, khi, klo, nullptr, nullptr,
            sp, nullptr, nullptr, nullptr, nullptr,
            TT, TT, HH, (long)TT * HH, (long)TT * HH, (long)TT * TT, scale);
    }

    // 4) causal softmax -> P hi/lo (vectorized, 128-boundary zero-fill)
    softmax_split_kernel<<<BB * TT, 256>>>(sp, phi, plo);

    // 5) out = P @ V: V consumed in natural [t][h] layout via ldmatrix.trans,
    //    k-loop bounded by causality, longest tiles first.
    {
        dim3 grid(HH / 128, TT / 128, BB);
        mma_gemm<2, 0, 1><<<grid, 256, GEMM_SMEM_BYTES>>>(
            phi, plo, vhi, vlo, nullptr, nullptr,
            out, nullptr, nullptr, nullptr, nullptr,
            TT, HH, TT, (long)TT * TT, (long)TT * HH, (long)TT * HH, 1.0f);
    }
}